// round 5
// baseline (speedup 1.0000x reference)
#include <cuda_runtime.h>

#define T_LEN 2048
#define E_N   19
#define B_N   64
#define H_N   32

typedef unsigned long long u64;

// final hidden states: [b][e][dir*32+l]
__device__ float g_hfinal[B_N * E_N * 64];

#define C_SIG  (-1.4426950408889634f)
#define C_TANH (-2.8853900817779268f)

__device__ __forceinline__ u64 ffma2(u64 a, u64 b, u64 c) {
    u64 d;
    asm("fma.rn.f32x2 %0, %1, %2, %3;" : "=l"(d) : "l"(a), "l"(b), "l"(c));
    return d;
}
__device__ __forceinline__ u64 pack2(float lo, float hi) {
    u64 r;
    asm("mov.b64 %0, {%1, %2};" : "=l"(r) : "f"(lo), "f"(hi));
    return r;
}
__device__ __forceinline__ void unpack2(u64 v, float &lo, float &hi) {
    asm("mov.b64 {%0, %1}, %2;" : "=f"(lo), "=f"(hi) : "l"(v));
}
// 1/(1+2^a): pre-activations arrive pre-scaled by -log2(e) (or -2log2e for tanh)
__device__ __forceinline__ float sig_pre(float a) {
    float e, r;
    asm("ex2.approx.f32 %0, %1;" : "=f"(e) : "f"(a));
    asm("rcp.approx.f32 %0, %1;" : "=f"(r) : "f"(1.0f + e));
    return r;
}

// One warp = one (e,dir) x NI batch items. Lane l owns hidden unit l.
// W_hh register-resident, (i,f)/(g,o) f32x2-packed, activation scales folded.
// h exchanged via dup-packed smem double buffer (broadcast LDS.128), warp-local sync.
template <int NI>
__device__ __forceinline__ void run_lstm(
    const float* __restrict__ x, const float* __restrict__ w_ih,
    const float* __restrict__ w_hh, const float* __restrict__ b_ih,
    const float* __restrict__ b_hh,
    int ed, int b0, int lane, u64* hb /* [2][3][H_N] */)
{
    const int e = ed >> 1;
    const int d = ed & 1;

    // ---- recurrent weights -> registers, gate-pair packed, scales folded ----
    const float* Wrow = w_hh + (ed * 4 * H_N + lane) * H_N;
    u64 Wif[H_N], Wgo[H_N];
#pragma unroll
    for (int j = 0; j < H_N / 4; j++) {
        float4 wi = *(const float4*)(Wrow + 0 * H_N * H_N + 4 * j);
        float4 wf = *(const float4*)(Wrow + 1 * H_N * H_N + 4 * j);
        float4 wg = *(const float4*)(Wrow + 2 * H_N * H_N + 4 * j);
        float4 wo = *(const float4*)(Wrow + 3 * H_N * H_N + 4 * j);
        Wif[4*j+0] = pack2(C_SIG * wi.x, C_SIG * wf.x);
        Wif[4*j+1] = pack2(C_SIG * wi.y, C_SIG * wf.y);
        Wif[4*j+2] = pack2(C_SIG * wi.z, C_SIG * wf.z);
        Wif[4*j+3] = pack2(C_SIG * wi.w, C_SIG * wf.w);
        Wgo[4*j+0] = pack2(C_TANH * wg.x, C_SIG * wo.x);
        Wgo[4*j+1] = pack2(C_TANH * wg.y, C_SIG * wo.y);
        Wgo[4*j+2] = pack2(C_TANH * wg.z, C_SIG * wo.z);
        Wgo[4*j+3] = pack2(C_TANH * wg.w, C_SIG * wo.w);
    }
    const int gb = ed * 4 * H_N + lane;
    const u64 bias_if = pack2(C_SIG  * (b_ih[gb]           + b_hh[gb]),
                              C_SIG  * (b_ih[gb +     H_N] + b_hh[gb +     H_N]));
    const u64 bias_go = pack2(C_TANH * (b_ih[gb + 2 * H_N] + b_hh[gb + 2 * H_N]),
                              C_SIG  * (b_ih[gb + 3 * H_N] + b_hh[gb + 3 * H_N]));
    const u64 wih_if  = pack2(C_SIG  * w_ih[gb],           C_SIG * w_ih[gb + H_N]);
    const u64 wih_go  = pack2(C_TANH * w_ih[gb + 2 * H_N], C_SIG * w_ih[gb + 3 * H_N]);

    // ---- state init ----
    float c[NI], hv[NI], xc[NI];
    const float* xp[NI];
    const int tstart = d ? (T_LEN - 1) : 0;
    const int stride = d ? -E_N : E_N;
#pragma unroll
    for (int i = 0; i < NI; i++) {
        c[i] = 0.f; hv[i] = 0.f;
        hb[0 * 3 * H_N + i * H_N + lane] = 0ull;
        xp[i] = x + ((long long)(b0 + i) * T_LEN + tstart) * E_N + e;
        xc[i] = __ldg(xp[i]);
    }
    __syncwarp();

    int cur = 0;
#pragma unroll 1
    for (int t = 0; t < T_LEN; t++) {
        float xn[NI];
        if (t < T_LEN - 1) {
#pragma unroll
            for (int i = 0; i < NI; i++) xp[i] += stride;
        }
#pragma unroll
        for (int i = 0; i < NI; i++) xn[i] = __ldg(xp[i]);

        u64 aif[NI], ago[NI];
#pragma unroll
        for (int i = 0; i < NI; i++) {
            u64 xd = pack2(xc[i], xc[i]);
            aif[i] = ffma2(xd, wih_if, bias_if);
            ago[i] = ffma2(xd, wih_go, bias_go);
        }

        const ulonglong2* hbc = (const ulonglong2*)(hb + cur * 3 * H_N);
#pragma unroll
        for (int j = 0; j < H_N / 2; j++) {
#pragma unroll
            for (int i = 0; i < NI; i++) {
                ulonglong2 hh = hbc[i * (H_N / 2) + j];   // broadcast LDS.128
                aif[i] = ffma2(Wif[2*j],   hh.x, aif[i]);
                ago[i] = ffma2(Wgo[2*j],   hh.x, ago[i]);
                aif[i] = ffma2(Wif[2*j+1], hh.y, aif[i]);
                ago[i] = ffma2(Wgo[2*j+1], hh.y, ago[i]);
            }
        }

        const int nxt = cur ^ 1;
#pragma unroll
        for (int i = 0; i < NI; i++) {
            float ai, af, ag, ao;
            unpack2(aif[i], ai, af);
            unpack2(ago[i], ag, ao);
            const float si = sig_pre(ai);
            const float sf = sig_pre(af);
            const float tg = fmaf(2.f, sig_pre(ag), -1.f);
            const float so = sig_pre(ao);
            c[i] = fmaf(sf, c[i], si * tg);
            const float tc = fmaf(2.f, sig_pre(c[i] * C_TANH), -1.f);
            hv[i] = so * tc;
            hb[nxt * 3 * H_N + i * H_N + lane] = pack2(hv[i], hv[i]);
        }
        __syncwarp();
        cur = nxt;
#pragma unroll
        for (int i = 0; i < NI; i++) xc[i] = xn[i];
    }

#pragma unroll
    for (int i = 0; i < NI; i++)
        g_hfinal[((b0 + i) * E_N + e) * 64 + d * 32 + lane] = hv[i];
}

// 1184 single-warp CTAs -> exactly 8 CTAs/SM, 2 warps/SMSP.
// Warps 0..991: ed = W/31 (eds 0..31); k<29 -> NI=2 (b0=2k), k=29/30 -> NI=3.
// Warps 992..1183: eds 32..37, 32 warps each, NI=2.
__global__ void __launch_bounds__(32)
lstm_kernel(const float* __restrict__ x,
            const float* __restrict__ w_ih,
            const float* __restrict__ w_hh,
            const float* __restrict__ b_ih,
            const float* __restrict__ b_hh)
{
    __shared__ u64 hbuf[2][3][H_N];
    const int lane = threadIdx.x;
    const int W    = blockIdx.x;

    int ed, k;
    if (W < 992) { ed = W / 31; k = W - ed * 31; }
    else         { int r = W - 992; ed = 32 + (r >> 5); k = r & 31; }

    u64* hb = &hbuf[0][0][0];
    if (W < 992 && k >= 29) {
        run_lstm<3>(x, w_ih, w_hh, b_ih, b_hh, ed, 58 + 3 * (k - 29), lane, hb);
    } else {
        run_lstm<2>(x, w_ih, w_hh, b_ih, b_hh, ed, 2 * k, lane, hb);
    }
}

// Per-batch epilogue: per-electrode LayerNorm over 64 features, electrode mean, FC.
__global__ void __launch_bounds__(64)
head_kernel(const float* __restrict__ ln_gamma,
            const float* __restrict__ ln_beta,
            const float* __restrict__ fc_w,
            const float* __restrict__ fc_b,
            float* __restrict__ out)
{
    const int b = blockIdx.x;
    const int f = threadIdx.x;
    __shared__ float red[4];
    const float* hbp = g_hfinal + b * (E_N * 64);

    float pooled = 0.f;
    for (int e = 0; e < E_N; e++) {
        float v = hbp[e * 64 + f];
        float s = v, s2 = v * v;
#pragma unroll
        for (int off = 16; off; off >>= 1) {
            s  += __shfl_xor_sync(0xffffffffu, s,  off);
            s2 += __shfl_xor_sync(0xffffffffu, s2, off);
        }
        if ((f & 31) == 0) { red[(f >> 5) * 2] = s; red[(f >> 5) * 2 + 1] = s2; }
        __syncthreads();
        float S = red[0] + red[2], S2 = red[1] + red[3];
        __syncthreads();
        float mu  = S * (1.0f / 64.0f);
        float var = fmaf(-mu, mu, S2 * (1.0f / 64.0f));
        float nv  = (v - mu) * rsqrtf(var + 1e-5f);
        pooled += fmaf(nv, ln_gamma[e * 64 + f], ln_beta[e * 64 + f]);
    }
    pooled *= (1.0f / (float)E_N);

    float a = pooled * fc_w[f];
#pragma unroll
    for (int off = 16; off; off >>= 1) a += __shfl_xor_sync(0xffffffffu, a, off);
    if ((f & 31) == 0) red[f >> 5] = a;
    __syncthreads();
    if (f == 0) out[b] = red[0] + red[1] + fc_b[0];
}

extern "C" void kernel_launch(void* const* d_in, const int* in_sizes, int n_in,
                              void* d_out, int out_size) {
    const float* x        = (const float*)d_in[0];
    const float* w_ih     = (const float*)d_in[1];
    const float* w_hh     = (const float*)d_in[2];
    const float* b_ih     = (const float*)d_in[3];
    const float* b_hh     = (const float*)d_in[4];
    const float* ln_gamma = (const float*)d_in[5];
    const float* ln_beta  = (const float*)d_in[6];
    const float* fc_w     = (const float*)d_in[7];
    const float* fc_b     = (const float*)d_in[8];
    float* out = (float*)d_out;

    lstm_kernel<<<1184, 32>>>(x, w_ih, w_hh, b_ih, b_hh);
    head_kernel<<<B_N, 64>>>(ln_gamma, ln_beta, fc_w, fc_b, out);
}

// round 6
// speedup vs baseline: 1.9153x; 1.9153x over previous
#include <cuda_runtime.h>
#include <cuda_bf16.h>

#define T_LEN 2048
#define E_N   19
#define B_N   64

typedef unsigned int u32;

#define C_SIG  (-1.4426950408889634f)
#define C_TANH (-2.8853900817779268f)

// final hidden states: [b][e][dir*32+u]
__device__ float g_hfinal[B_N * E_N * 64];

// 1/(1+2^a): pre-activations arrive pre-scaled by -log2(e) (or -2log2e for tanh)
__device__ __forceinline__ float sig_pre(float a) {
    float e, r;
    asm("ex2.approx.f32 %0, %1;" : "=f"(e) : "f"(a));
    asm("rcp.approx.f32 %0, %1;" : "=f"(r) : "f"(1.0f + e));
    return r;
}

__device__ __forceinline__ u32 pack_bf2(float lo, float hi) {
    __nv_bfloat162 p;
    p.x = __float2bfloat16(lo);   // low 16 bits = lower k index
    p.y = __float2bfloat16(hi);
    return *(u32*)&p;
}

// D += A(16x16 bf16, row-major) * B(16x8 bf16, col-major), fp32 accumulate
__device__ __forceinline__ void mma16816(float d[4], const u32 a[4], u32 b0, u32 b1) {
    asm volatile(
        "mma.sync.aligned.m16n8k16.row.col.f32.bf16.bf16.f32 "
        "{%0,%1,%2,%3}, {%4,%5,%6,%7}, {%8,%9}, {%0,%1,%2,%3};"
        : "+f"(d[0]), "+f"(d[1]), "+f"(d[2]), "+f"(d[3])
        : "r"(a[0]), "r"(a[1]), "r"(a[2]), "r"(a[3]), "r"(b0), "r"(b1));
}

// One CTA = one (e,dir) x 8 batch items, 4 warps, warp w owns gate w.
// Per step per warp: 8 HMMA over K=64 = exact [Whi|Wlo] @ [hhi;hlo] split.
// Gates exchanged via smem transpose; c,h in fixed per-thread registers
// (thread tid -> item = tid&7, units u0 = tid>>3 and u0+16).
__global__ void __launch_bounds__(128)
lstm_kernel(const float* __restrict__ x,      // [B, T, E]
            const float* __restrict__ w_ih,   // [E, 2, 128]
            const float* __restrict__ w_hh,   // [E, 2, 128, 32]
            const float* __restrict__ b_ih,   // [E, 2, 128]
            const float* __restrict__ b_hh)   // [E, 2, 128]
{
    __shared__ __nv_bfloat16 bsm[8][72];   // [item][k: 0..31 hhi, 32..63 hlo] (+pad)
    __shared__ float gbuf[4][32][9];       // [gate][unit][item] (+pad)
    __shared__ float xs[2][8];             // x double buffer

    const int tid  = threadIdx.x;
    const int w    = tid >> 5;     // gate id
    const int lane = tid & 31;
    const int grp  = lane >> 2;    // 0..7
    const int tig  = lane & 3;     // 0..3

    const int ed = blockIdx.x >> 3;
    const int b0 = (blockIdx.x & 7) * 8;
    const int e  = ed >> 1;
    const int d  = ed & 1;

    const float C = (w == 2) ? C_TANH : C_SIG;

    // ---- build A fragments: rows = gate-w rows of W_hh (scale folded),
    //      K = 64: cols 0..31 bf16-hi, 32..63 bf16-lo residual ----
    u32 A[2][4][4];
    {
        const float* Wp = w_hh + (ed * 128 + w * 32) * 32;
        auto wsplit = [&](int r, int kk) -> float {
            int k = kk & 31;
            float wv = Wp[r * 32 + k] * C;
            float hi = __bfloat162float(__float2bfloat16(wv));
            return (kk < 32) ? hi : (wv - hi);
        };
#pragma unroll
        for (int mt = 0; mt < 2; mt++) {
#pragma unroll
            for (int kt = 0; kt < 4; kt++) {
                const int r0 = 16 * mt + grp;
                const int kb = 16 * kt + 2 * tig;
                A[mt][kt][0] = pack_bf2(wsplit(r0,     kb),     wsplit(r0,     kb + 1));
                A[mt][kt][1] = pack_bf2(wsplit(r0 + 8, kb),     wsplit(r0 + 8, kb + 1));
                A[mt][kt][2] = pack_bf2(wsplit(r0,     kb + 8), wsplit(r0,     kb + 9));
                A[mt][kt][3] = pack_bf2(wsplit(r0 + 8, kb + 8), wsplit(r0 + 8, kb + 9));
            }
        }
    }

    // per-thread input weight / bias for its 4 (gate-w, unit) rows
    float wihC[4], biasC[4];
#pragma unroll
    for (int q = 0; q < 4; q++) {
        const int u   = grp + 16 * (q >> 1) + 8 * (q & 1);
        const int row = ed * 128 + w * 32 + u;
        wihC[q]  = C * w_ih[row];
        biasC[q] = C * (b_ih[row] + b_hh[row]);
    }

    // ---- zero h smem (h0 = 0), init x buffers ----
    for (int i = tid; i < (int)(sizeof(bsm) / 4); i += 128) ((u32*)bsm)[i] = 0u;

    const int tstart = d ? (T_LEN - 1) : 0;
    const int stride = d ? -E_N : E_N;
    const float* xp = x + ((long long)(b0 + (tid & 7)) * T_LEN + tstart) * E_N + e;
    float xnext = 0.f;
    if (tid < 8) {
        xs[0][tid] = __ldg(xp);
        xp += stride;
        xnext = __ldg(xp);
    }

    // c-phase ownership
    const int item = tid & 7;
    const int u0   = tid >> 4 == 0 ? (tid >> 3) : (tid >> 3) & 15;  // (tid>>3) & 15
    const int uu0  = (tid >> 3) & 15;
    const int uu1  = uu0 + 16;
    float c0 = 0.f, c1 = 0.f, h0 = 0.f, h1 = 0.f;
    (void)u0;

    __syncthreads();

#pragma unroll 1
    for (int t = 0; t < T_LEN; t++) {
        // ---- B fragments from smem (conflict-free) ----
        u32 B0[4], B1[4];
#pragma unroll
        for (int kt = 0; kt < 4; kt++) {
            B0[kt] = *(const u32*)&bsm[grp][16 * kt + 2 * tig];
            B1[kt] = *(const u32*)&bsm[grp][16 * kt + 2 * tig + 8];
        }

        // ---- 8 HMMA: gates[32x8] for gate w ----
        float D[2][4];
#pragma unroll
        for (int mt = 0; mt < 2; mt++) {
            D[mt][0] = 0.f; D[mt][1] = 0.f; D[mt][2] = 0.f; D[mt][3] = 0.f;
#pragma unroll
            for (int kt = 0; kt < 4; kt++)
                mma16816(D[mt], A[mt][kt], B0[kt], B1[kt]);
        }

        // ---- activations, write transposed to gbuf ----
        const float xv0 = xs[t & 1][2 * tig];
        const float xv1 = xs[t & 1][2 * tig + 1];
#pragma unroll
        for (int mt = 0; mt < 2; mt++) {
#pragma unroll
            for (int j = 0; j < 4; j++) {
                const int q = mt * 2 + (j >> 1);
                const float xv = (j & 1) ? xv1 : xv0;
                float pre = fmaf(xv, wihC[q], D[mt][j] + biasC[q]);
                float s = sig_pre(pre);
                if (w == 2) s = fmaf(2.f, s, -1.f);     // tanh for g gate
                const int u = grp + 16 * mt + 8 * (j >> 1);
                gbuf[w][u][2 * tig + (j & 1)] = s;
            }
        }
        __syncthreads();

        // ---- c/h update (thread owns item, units uu0 & uu1) ----
        {
            const float gi0 = gbuf[0][uu0][item], gi1 = gbuf[0][uu1][item];
            const float gf0 = gbuf[1][uu0][item], gf1 = gbuf[1][uu1][item];
            const float gg0 = gbuf[2][uu0][item], gg1 = gbuf[2][uu1][item];
            const float go0 = gbuf[3][uu0][item], go1 = gbuf[3][uu1][item];
            c0 = fmaf(gf0, c0, gi0 * gg0);
            c1 = fmaf(gf1, c1, gi1 * gg1);
            const float tc0 = fmaf(2.f, sig_pre(c0 * C_TANH), -1.f);
            const float tc1 = fmaf(2.f, sig_pre(c1 * C_TANH), -1.f);
            h0 = go0 * tc0;
            h1 = go1 * tc1;
            const __nv_bfloat16 bh0 = __float2bfloat16(h0);
            const __nv_bfloat16 bh1 = __float2bfloat16(h1);
            bsm[item][uu0]      = bh0;
            bsm[item][uu1]      = bh1;
            bsm[item][32 + uu0] = __float2bfloat16(h0 - __bfloat162float(bh0));
            bsm[item][32 + uu1] = __float2bfloat16(h1 - __bfloat162float(bh1));
        }

        // ---- x pipeline ----
        if (tid < 8) {
            xs[(t + 1) & 1][tid] = xnext;
            if (t + 2 < T_LEN) xp += stride;
            xnext = __ldg(xp);
        }
        __syncthreads();
    }

    g_hfinal[((b0 + item) * E_N + e) * 64 + d * 32 + uu0] = h0;
    g_hfinal[((b0 + item) * E_N + e) * 64 + d * 32 + uu1] = h1;
}

// Per-batch epilogue: per-electrode LayerNorm over 64 features, electrode mean, FC.
__global__ void __launch_bounds__(64)
head_kernel(const float* __restrict__ ln_gamma,
            const float* __restrict__ ln_beta,
            const float* __restrict__ fc_w,
            const float* __restrict__ fc_b,
            float* __restrict__ out)
{
    const int b = blockIdx.x;
    const int f = threadIdx.x;
    __shared__ float red[4];
    const float* hbp = g_hfinal + b * (E_N * 64);

    float pooled = 0.f;
    for (int e = 0; e < E_N; e++) {
        float v = hbp[e * 64 + f];
        float s = v, s2 = v * v;
#pragma unroll
        for (int off = 16; off; off >>= 1) {
            s  += __shfl_xor_sync(0xffffffffu, s,  off);
            s2 += __shfl_xor_sync(0xffffffffu, s2, off);
        }
        if ((f & 31) == 0) { red[(f >> 5) * 2] = s; red[(f >> 5) * 2 + 1] = s2; }
        __syncthreads();
        float S = red[0] + red[2], S2 = red[1] + red[3];
        __syncthreads();
        float mu  = S * (1.0f / 64.0f);
        float var = fmaf(-mu, mu, S2 * (1.0f / 64.0f));
        float nv  = (v - mu) * rsqrtf(var + 1e-5f);
        pooled += fmaf(nv, ln_gamma[e * 64 + f], ln_beta[e * 64 + f]);
    }
    pooled *= (1.0f / (float)E_N);

    float a = pooled * fc_w[f];
#pragma unroll
    for (int off = 16; off; off >>= 1) a += __shfl_xor_sync(0xffffffffu, a, off);
    if ((f & 31) == 0) red[f >> 5] = a;
    __syncthreads();
    if (f == 0) out[b] = red[0] + red[1] + fc_b[0];
}

extern "C" void kernel_launch(void* const* d_in, const int* in_sizes, int n_in,
                              void* d_out, int out_size) {
    const float* x        = (const float*)d_in[0];
    const float* w_ih     = (const float*)d_in[1];
    const float* w_hh     = (const float*)d_in[2];
    const float* b_ih     = (const float*)d_in[3];
    const float* b_hh     = (const float*)d_in[4];
    const float* ln_gamma = (const float*)d_in[5];
    const float* ln_beta  = (const float*)d_in[6];
    const float* fc_w     = (const float*)d_in[7];
    const float* fc_b     = (const float*)d_in[8];
    float* out = (float*)d_out;

    lstm_kernel<<<E_N * 2 * 8, 128>>>(x, w_ih, w_hh, b_ih, b_hh);
    head_kernel<<<B_N, 64>>>(ln_gamma, ln_beta, fc_w, fc_b, out);
}

// round 7
// speedup vs baseline: 2.7335x; 1.4272x over previous
#include <cuda_runtime.h>
#include <cuda_fp16.h>

#define T_LEN 2048
#define E_N   19
#define B_N   64

typedef unsigned int u32;

// final hidden states: [b][e][dir*32+u]
__device__ float g_hfinal[B_N * E_N * 64];

__device__ __forceinline__ float tanh_ap(float x) {
    float r;
    asm("tanh.approx.f32 %0, %1;" : "=f"(r) : "f"(x));
    return r;
}

__device__ __forceinline__ u32 pack_hf2(float lo, float hi) {
    __half2 p;
    p.x = __float2half(lo);    // low 16 bits = lower k index
    p.y = __float2half(hi);
    return *(u32*)&p;
}

// D += A(16x16 fp16, row-major) * B(16x8 fp16, col-major), fp32 accumulate
__device__ __forceinline__ void mma16816(float d[4], const u32 a[4], u32 b0, u32 b1) {
    asm volatile(
        "mma.sync.aligned.m16n8k16.row.col.f32.f16.f16.f32 "
        "{%0,%1,%2,%3}, {%4,%5,%6,%7}, {%8,%9}, {%0,%1,%2,%3};"
        : "+f"(d[0]), "+f"(d[1]), "+f"(d[2]), "+f"(d[3])
        : "r"(a[0]), "r"(a[1]), "r"(a[2]), "r"(a[3]), "r"(b0), "r"(b1));
}

// One CTA = one (e,dir) x 8 batch items, 4 warps, warp w owns gate w.
// Per step per warp: 4 HMMA, K=32 (fp16 W, fp16 h).
// Sigmoid gates: 0.5*tanh(0.5*a)+0.5 with the 0.5 folded into W/bias (C=0.5);
// g gate: tanh direct (C=1). All activations are single MUFU.TANH.
__global__ void __launch_bounds__(128)
lstm_kernel(const float* __restrict__ x,      // [B, T, E]
            const float* __restrict__ w_ih,   // [E, 2, 128]
            const float* __restrict__ w_hh,   // [E, 2, 128, 32]
            const float* __restrict__ b_ih,   // [E, 2, 128]
            const float* __restrict__ b_hh)   // [E, 2, 128]
{
    __shared__ __half bsm[8][40];      // [item][unit] fp16 h (+pad: 40 halves/row)
    __shared__ float gbuf[4][32][9];   // [gate][unit][item] (+pad)
    __shared__ float xs[2][8];         // x double buffer

    const int tid  = threadIdx.x;
    const int w    = tid >> 5;     // gate id
    const int lane = tid & 31;
    const int grp  = lane >> 2;    // 0..7
    const int tig  = lane & 3;     // 0..3

    const int ed = blockIdx.x >> 3;
    const int b0 = (blockIdx.x & 7) * 8;
    const int e  = ed >> 1;
    const int d  = ed & 1;

    const float C = (w == 2) ? 1.0f : 0.5f;

    // ---- A fragments: gate-w rows of W_hh, scale folded, fp16, K=32 ----
    u32 A[2][2][4];
    {
        const float* Wp = w_hh + (ed * 128 + w * 32) * 32;
        auto wq = [&](int r, int k) -> float { return Wp[r * 32 + k] * C; };
#pragma unroll
        for (int mt = 0; mt < 2; mt++) {
#pragma unroll
            for (int kt = 0; kt < 2; kt++) {
                const int r0 = 16 * mt + grp;
                const int kb = 16 * kt + 2 * tig;
                A[mt][kt][0] = pack_hf2(wq(r0,     kb),     wq(r0,     kb + 1));
                A[mt][kt][1] = pack_hf2(wq(r0 + 8, kb),     wq(r0 + 8, kb + 1));
                A[mt][kt][2] = pack_hf2(wq(r0,     kb + 8), wq(r0,     kb + 9));
                A[mt][kt][3] = pack_hf2(wq(r0 + 8, kb + 8), wq(r0 + 8, kb + 9));
            }
        }
    }

    // per-thread input weight / bias for its 4 (gate-w, unit) rows
    float wihC[4], biasC[4];
#pragma unroll
    for (int q = 0; q < 4; q++) {
        const int u   = grp + 16 * (q >> 1) + 8 * (q & 1);
        const int row = ed * 128 + w * 32 + u;
        wihC[q]  = C * w_ih[row];
        biasC[q] = C * (b_ih[row] + b_hh[row]);
    }

    // ---- zero h smem (h0 = 0), init x pipeline ----
    for (int i = tid; i < (int)(sizeof(bsm) / 4); i += 128) ((u32*)bsm)[i] = 0u;

    const int tstart = d ? (T_LEN - 1) : 0;
    const int stride = d ? -E_N : E_N;
    const float* xp = x + ((long long)(b0 + (tid & 7)) * T_LEN + tstart) * E_N + e;
    float xnext = 0.f;
    if (tid < 8) {
        xs[0][tid] = __ldg(xp);
        xp += stride;
        xnext = __ldg(xp);
    }

    const int item = tid & 7;
    const int uu0  = (tid >> 3) & 15;
    const int uu1  = uu0 + 16;
    float c0 = 0.f, c1 = 0.f, h0 = 0.f, h1 = 0.f;

    __syncthreads();

#pragma unroll 1
    for (int t = 0; t < T_LEN; t++) {
        // ---- B fragments from smem (conflict-free: row stride 20 words) ----
        u32 B0[2], B1[2];
#pragma unroll
        for (int kt = 0; kt < 2; kt++) {
            B0[kt] = *(const u32*)&bsm[grp][16 * kt + 2 * tig];
            B1[kt] = *(const u32*)&bsm[grp][16 * kt + 2 * tig + 8];
        }

        // ---- 4 HMMA: gates[32x8] for gate w ----
        float D[2][4];
#pragma unroll
        for (int mt = 0; mt < 2; mt++) {
            D[mt][0] = 0.f; D[mt][1] = 0.f; D[mt][2] = 0.f; D[mt][3] = 0.f;
            mma16816(D[mt], A[mt][0], B0[0], B1[0]);
            mma16816(D[mt], A[mt][1], B0[1], B1[1]);
        }

        // ---- activations (1 MUFU each), write transposed to gbuf ----
        const float xv0 = xs[t & 1][2 * tig];
        const float xv1 = xs[t & 1][2 * tig + 1];
#pragma unroll
        for (int mt = 0; mt < 2; mt++) {
#pragma unroll
            for (int j = 0; j < 4; j++) {
                const int q = mt * 2 + (j >> 1);
                const float xv = (j & 1) ? xv1 : xv0;
                const float pre = fmaf(xv, wihC[q], D[mt][j] + biasC[q]);
                float s = tanh_ap(pre);
                if (w != 2) s = fmaf(0.5f, s, 0.5f);     // sigmoid gates
                const int u = grp + 16 * mt + 8 * (j >> 1);
                gbuf[w][u][2 * tig + (j & 1)] = s;
            }
        }
        __syncthreads();

        // ---- c/h update (thread owns item, units uu0 & uu1) ----
        {
            const float gi0 = gbuf[0][uu0][item], gi1 = gbuf[0][uu1][item];
            const float gf0 = gbuf[1][uu0][item], gf1 = gbuf[1][uu1][item];
            const float gg0 = gbuf[2][uu0][item], gg1 = gbuf[2][uu1][item];
            const float go0 = gbuf[3][uu0][item], go1 = gbuf[3][uu1][item];
            c0 = fmaf(gf0, c0, gi0 * gg0);
            c1 = fmaf(gf1, c1, gi1 * gg1);
            h0 = go0 * tanh_ap(c0);
            h1 = go1 * tanh_ap(c1);
            bsm[item][uu0] = __float2half(h0);
            bsm[item][uu1] = __float2half(h1);
        }

        // ---- x pipeline ----
        if (tid < 8) {
            xs[(t + 1) & 1][tid] = xnext;
            if (t + 2 < T_LEN) xp += stride;
            xnext = __ldg(xp);
        }
        __syncthreads();
    }

    g_hfinal[((b0 + item) * E_N + e) * 64 + d * 32 + uu0] = h0;
    g_hfinal[((b0 + item) * E_N + e) * 64 + d * 32 + uu1] = h1;
}

// Per-batch epilogue: per-electrode LayerNorm over 64 features, electrode mean, FC.
__global__ void __launch_bounds__(64)
head_kernel(const float* __restrict__ ln_gamma,
            const float* __restrict__ ln_beta,
            const float* __restrict__ fc_w,
            const float* __restrict__ fc_b,
            float* __restrict__ out)
{
    const int b = blockIdx.x;
    const int f = threadIdx.x;
    __shared__ float red[4];
    const float* hbp = g_hfinal + b * (E_N * 64);

    float pooled = 0.f;
    for (int e = 0; e < E_N; e++) {
        float v = hbp[e * 64 + f];
        float s = v, s2 = v * v;
#pragma unroll
        for (int off = 16; off; off >>= 1) {
            s  += __shfl_xor_sync(0xffffffffu, s,  off);
            s2 += __shfl_xor_sync(0xffffffffu, s2, off);
        }
        if ((f & 31) == 0) { red[(f >> 5) * 2] = s; red[(f >> 5) * 2 + 1] = s2; }
        __syncthreads();
        float S = red[0] + red[2], S2 = red[1] + red[3];
        __syncthreads();
        float mu  = S * (1.0f / 64.0f);
        float var = fmaf(-mu, mu, S2 * (1.0f / 64.0f));
        float nv  = (v - mu) * rsqrtf(var + 1e-5f);
        pooled += fmaf(nv, ln_gamma[e * 64 + f], ln_beta[e * 64 + f]);
    }
    pooled *= (1.0f / (float)E_N);

    float a = pooled * fc_w[f];
#pragma unroll
    for (int off = 16; off; off >>= 1) a += __shfl_xor_sync(0xffffffffu, a, off);
    if ((f & 31) == 0) red[f >> 5] = a;
    __syncthreads();
    if (f == 0) out[b] = red[0] + red[1] + fc_b[0];
}

extern "C" void kernel_launch(void* const* d_in, const int* in_sizes, int n_in,
                              void* d_out, int out_size) {
    const float* x        = (const float*)d_in[0];
    const float* w_ih     = (const float*)d_in[1];
    const float* w_hh     = (const float*)d_in[2];
    const float* b_ih     = (const float*)d_in[3];
    const float* b_hh     = (const float*)d_in[4];
    const float* ln_gamma = (const float*)d_in[5];
    const float* ln_beta  = (const float*)d_in[6];
    const float* fc_w     = (const float*)d_in[7];
    const float* fc_b     = (const float*)d_in[8];
    float* out = (float*)d_out;

    lstm_kernel<<<E_N * 2 * 8, 128>>>(x, w_ih, w_hh, b_ih, b_hh);
    head_kernel<<<B_N, 64>>>(ln_gamma, ln_beta, fc_w, fc_b, out);
}

// round 8
// speedup vs baseline: 3.8496x; 1.4083x over previous
#include <cuda_runtime.h>
#include <cuda_fp16.h>

#define T_LEN 2048
#define E_N   19
#define B_N   64

typedef unsigned int u32;

// final hidden states: [b][e][dir*32+u]
__device__ float g_hfinal[B_N * E_N * 64];

__device__ __forceinline__ float tanh_ap(float x) {
    float r;
    asm("tanh.approx.f32 %0, %1;" : "=f"(r) : "f"(x));
    return r;
}

__device__ __forceinline__ u32 pack_hf2(float lo, float hi) {
    __half2 p;
    p.x = __float2half(lo);    // low 16 bits = lower k index
    p.y = __float2half(hi);
    return *(u32*)&p;
}

// D += A(16x16 fp16, row-major) * B(16x8 fp16, col-major), fp32 accumulate
__device__ __forceinline__ void mma16816(float d[4], const u32 a[4], u32 b0, u32 b1) {
    asm volatile(
        "mma.sync.aligned.m16n8k16.row.col.f32.f16.f16.f32 "
        "{%0,%1,%2,%3}, {%4,%5,%6,%7}, {%8,%9}, {%0,%1,%2,%3};"
        : "+f"(d[0]), "+f"(d[1]), "+f"(d[2]), "+f"(d[3])
        : "r"(a[0]), "r"(a[1]), "r"(a[2]), "r"(a[3]), "r"(b0), "r"(b1));
}

// One CTA = one (e,dir) x 8 batch items, 4 warps.
// Warp w owns UNITS 8w..8w+7. Its 32 M-rows are permuted as
// [i-gate(8 units); f(8); g(8); o(8)], so after the MMA each thread
// (grp,tig) holds ALL FOUR gates for unit 8w+grp, items 2tig & 2tig+1
// -> c/h update is thread-local, zero gate transpose, ONE barrier/step.
// Sigmoid gates: 0.5*tanh(0.5a)+0.5 (0.5 folded into W/bias); g gate tanh.
__global__ void __launch_bounds__(128)
lstm_kernel(const float* __restrict__ x,      // [B, T, E]
            const float* __restrict__ w_ih,   // [E, 2, 128]
            const float* __restrict__ w_hh,   // [E, 2, 128, 32]
            const float* __restrict__ b_ih,   // [E, 2, 128]
            const float* __restrict__ b_hh)   // [E, 2, 128]
{
    __shared__ __half bsm[8][40];   // [item][unit] fp16 h (+pad)
    __shared__ float xs[2][8];      // x double buffer

    const int tid  = threadIdx.x;
    const int w    = tid >> 5;
    const int lane = tid & 31;
    const int grp  = lane >> 2;    // 0..7
    const int tig  = lane & 3;     // 0..3

    const int ed = blockIdx.x >> 3;
    const int b0 = (blockIdx.x & 7) * 8;
    const int e  = ed >> 1;
    const int d  = ed & 1;

    const int u = 8 * w + grp;     // unit owned by this thread

    // ---- A fragments: m-tile mt rows = [gate 2mt units; gate 2mt+1 units] ----
    u32 A[2][2][4];
    {
        const float* Wp = w_hh + ed * 128 * 32;
#pragma unroll
        for (int mt = 0; mt < 2; mt++) {
            const int g0 = 2 * mt, g1 = 2 * mt + 1;
            const float C0 = (g0 == 2) ? 1.0f : 0.5f;
            const float C1 = (g1 == 2) ? 1.0f : 0.5f;
            const float* r0 = Wp + (g0 * 32 + u) * 32;
            const float* r1 = Wp + (g1 * 32 + u) * 32;
#pragma unroll
            for (int kt = 0; kt < 2; kt++) {
                const int kb = 16 * kt + 2 * tig;
                A[mt][kt][0] = pack_hf2(r0[kb] * C0,     r0[kb + 1] * C0);
                A[mt][kt][1] = pack_hf2(r1[kb] * C1,     r1[kb + 1] * C1);
                A[mt][kt][2] = pack_hf2(r0[kb + 8] * C0, r0[kb + 9] * C0);
                A[mt][kt][3] = pack_hf2(r1[kb + 8] * C1, r1[kb + 9] * C1);
            }
        }
    }

    // input weight / bias for unit u, gates 0..3 (activation scale folded)
    float wihC[4], biasC[4];
#pragma unroll
    for (int g = 0; g < 4; g++) {
        const float Cg = (g == 2) ? 1.0f : 0.5f;
        const int row = ed * 128 + g * 32 + u;
        wihC[g]  = Cg * w_ih[row];
        biasC[g] = Cg * (b_ih[row] + b_hh[row]);
    }

    // ---- zero h smem (h0 = 0), init x pipeline ----
    for (int i = tid; i < (int)(sizeof(bsm) / 4); i += 128) ((u32*)bsm)[i] = 0u;

    const int tstart = d ? (T_LEN - 1) : 0;
    const int stride = d ? -E_N : E_N;
    const float* xp = x + ((long long)(b0 + (tid & 7)) * T_LEN + tstart) * E_N + e;
    float xnext = 0.f;
    if (tid < 8) {
        xs[0][tid] = __ldg(xp);
        xp += stride;
        xnext = __ldg(xp);
    }

    const int it0 = 2 * tig, it1 = 2 * tig + 1;
    float c0 = 0.f, c1 = 0.f, h0 = 0.f, h1 = 0.f;

    __syncthreads();

#pragma unroll 1
    for (int t = 0; t < T_LEN; t++) {
        // ---- seed accumulators with x*w_ih + bias (off the MMA chain) ----
        const float xv0 = xs[t & 1][it0];
        const float xv1 = xs[t & 1][it1];
        float D[2][4];
#pragma unroll
        for (int mt = 0; mt < 2; mt++) {
            D[mt][0] = fmaf(xv0, wihC[2 * mt],     biasC[2 * mt]);
            D[mt][1] = fmaf(xv1, wihC[2 * mt],     biasC[2 * mt]);
            D[mt][2] = fmaf(xv0, wihC[2 * mt + 1], biasC[2 * mt + 1]);
            D[mt][3] = fmaf(xv1, wihC[2 * mt + 1], biasC[2 * mt + 1]);
        }

        // ---- B fragments from smem ----
        u32 B0[2], B1[2];
#pragma unroll
        for (int kt = 0; kt < 2; kt++) {
            B0[kt] = *(const u32*)&bsm[grp][16 * kt + 2 * tig];
            B1[kt] = *(const u32*)&bsm[grp][16 * kt + 2 * tig + 8];
        }

        // ---- 4 HMMA: all four gates for unit u, items it0/it1 ----
#pragma unroll
        for (int mt = 0; mt < 2; mt++) {
            mma16816(D[mt], A[mt][0], B0[0], B1[0]);
            mma16816(D[mt], A[mt][1], B0[1], B1[1]);
        }

        // ---- thread-local activations + c/h update ----
        const float si0 = fmaf(0.5f, tanh_ap(D[0][0]), 0.5f);
        const float si1 = fmaf(0.5f, tanh_ap(D[0][1]), 0.5f);
        const float sf0 = fmaf(0.5f, tanh_ap(D[0][2]), 0.5f);
        const float sf1 = fmaf(0.5f, tanh_ap(D[0][3]), 0.5f);
        const float sg0 = tanh_ap(D[1][0]);
        const float sg1 = tanh_ap(D[1][1]);
        const float so0 = fmaf(0.5f, tanh_ap(D[1][2]), 0.5f);
        const float so1 = fmaf(0.5f, tanh_ap(D[1][3]), 0.5f);
        c0 = fmaf(sf0, c0, si0 * sg0);
        c1 = fmaf(sf1, c1, si1 * sg1);
        h0 = so0 * tanh_ap(c0);
        h1 = so1 * tanh_ap(c1);
        bsm[it0][u] = __float2half(h0);
        bsm[it1][u] = __float2half(h1);

        // ---- x pipeline ----
        if (tid < 8) {
            xs[(t + 1) & 1][tid] = xnext;
            if (t + 2 < T_LEN) xp += stride;
            xnext = __ldg(xp);
        }
        __syncthreads();
    }

    g_hfinal[((b0 + it0) * E_N + e) * 64 + d * 32 + u] = h0;
    g_hfinal[((b0 + it1) * E_N + e) * 64 + d * 32 + u] = h1;
}

// Per-batch epilogue: per-electrode LayerNorm over 64 features, electrode mean, FC.
__global__ void __launch_bounds__(64)
head_kernel(const float* __restrict__ ln_gamma,
            const float* __restrict__ ln_beta,
            const float* __restrict__ fc_w,
            const float* __restrict__ fc_b,
            float* __restrict__ out)
{
    const int b = blockIdx.x;
    const int f = threadIdx.x;
    __shared__ float red[4];
    const float* hbp = g_hfinal + b * (E_N * 64);

    float pooled = 0.f;
    for (int e = 0; e < E_N; e++) {
        float v = hbp[e * 64 + f];
        float s = v, s2 = v * v;
#pragma unroll
        for (int off = 16; off; off >>= 1) {
            s  += __shfl_xor_sync(0xffffffffu, s,  off);
            s2 += __shfl_xor_sync(0xffffffffu, s2, off);
        }
        if ((f & 31) == 0) { red[(f >> 5) * 2] = s; red[(f >> 5) * 2 + 1] = s2; }
        __syncthreads();
        float S = red[0] + red[2], S2 = red[1] + red[3];
        __syncthreads();
        float mu  = S * (1.0f / 64.0f);
        float var = fmaf(-mu, mu, S2 * (1.0f / 64.0f));
        float nv  = (v - mu) * rsqrtf(var + 1e-5f);
        pooled += fmaf(nv, ln_gamma[e * 64 + f], ln_beta[e * 64 + f]);
    }
    pooled *= (1.0f / (float)E_N);

    float a = pooled * fc_w[f];
#pragma unroll
    for (int off = 16; off; off >>= 1) a += __shfl_xor_sync(0xffffffffu, a, off);
    if ((f & 31) == 0) red[f >> 5] = a;
    __syncthreads();
    if (f == 0) out[b] = red[0] + red[1] + fc_b[0];
}

extern "C" void kernel_launch(void* const* d_in, const int* in_sizes, int n_in,
                              void* d_out, int out_size) {
    const float* x        = (const float*)d_in[0];
    const float* w_ih     = (const float*)d_in[1];
    const float* w_hh     = (const float*)d_in[2];
    const float* b_ih     = (const float*)d_in[3];
    const float* b_hh     = (const float*)d_in[4];
    const float* ln_gamma = (const float*)d_in[5];
    const float* ln_beta  = (const float*)d_in[6];
    const float* fc_w     = (const float*)d_in[7];
    const float* fc_b     = (const float*)d_in[8];
    float* out = (float*)d_out;

    lstm_kernel<<<E_N * 2 * 8, 128>>>(x, w_ih, w_hh, b_ih, b_hh);
    head_kernel<<<B_N, 64>>>(ln_gamma, ln_beta, fc_w, fc_b, out);
}